// round 13
// baseline (speedup 1.0000x reference)
#include <cuda_runtime.h>
#include <cuda_fp16.h>
#include <cstdint>

#define NB    8192
#define SH    136    // padded half stride (17x16B rows -> conflict-free ldmatrix/stmatrix)
#define ZSTH  136
#define NT1   256

// ---- kernel-1 shared memory (per CTA ~112KB -> 2 CTAs/SM) ----
#define OFF_B1   0        // 512
#define OFF_B2   512      // 512
#define OFF_B3   1024     // 128 (+pad)
#define OFF_W3T  1280     // 32*136*2 = 8704
#define OFF_H1   9984     // 128*136*2 = 34816   (zth overlaps this region in L3 phase)
#define OFF_H2   44800    // 34816
#define OFF_W2T  79616    // 34816 (persistent)
#define SMEM1    114432

// 64MB z scratch: [b][cp(16)][r/4(32)] uint4 (half2 pairs)
__device__ uint4 g_z[NB * 16 * 32];

__device__ __forceinline__ void mma16816(float* d, const uint32_t* a, const uint32_t* b) {
    asm volatile(
        "mma.sync.aligned.m16n8k16.row.col.f32.f16.f16.f32 "
        "{%0,%1,%2,%3},{%4,%5,%6,%7},{%8,%9},{%0,%1,%2,%3};\n"
        : "+f"(d[0]), "+f"(d[1]), "+f"(d[2]), "+f"(d[3])
        : "r"(a[0]), "r"(a[1]), "r"(a[2]), "r"(a[3]), "r"(b[0]), "r"(b[1]));
}

__device__ __forceinline__ void mma16808(float* d, const uint32_t* a, uint32_t b) {
    asm volatile(
        "mma.sync.aligned.m16n8k8.row.col.f32.f16.f16.f32 "
        "{%0,%1,%2,%3},{%4,%5},{%6},{%0,%1,%2,%3};\n"
        : "+f"(d[0]), "+f"(d[1]), "+f"(d[2]), "+f"(d[3])
        : "r"(a[0]), "r"(a[1]), "r"(b));
}

#define LDSM4(r, addr) \
    asm volatile("ldmatrix.sync.aligned.m8n8.x4.shared.b16 {%0,%1,%2,%3}, [%4];" \
                 : "=r"((r)[0]), "=r"((r)[1]), "=r"((r)[2]), "=r"((r)[3]) : "r"(addr))

#define STSM4(addr, r0, r1, r2, r3) \
    asm volatile("stmatrix.sync.aligned.m8n8.x4.shared.b16 [%0], {%1,%2,%3,%4};" \
                 :: "r"(addr), "r"(r0), "r"(r1), "r"(r2), "r"(r3))

__device__ __forceinline__ uint32_t packh2(float a, float b) {
    __half2 h = __floats2half2_rn(a, b);
    return *(uint32_t*)&h;
}
__device__ __forceinline__ uint32_t h2max(uint32_t a, uint32_t b) {
    __half2 r = __hmax2(*(__half2*)&a, *(__half2*)&b); return *(uint32_t*)&r;
}
__device__ __forceinline__ uint32_t h2min(uint32_t a, uint32_t b) {
    __half2 r = __hmin2(*(__half2*)&a, *(__half2*)&b); return *(uint32_t*)&r;
}
#define CEXH(a, b, dsc) do { uint32_t _hi = h2max(a, b), _lo = h2min(a, b); \
                             (a) = (dsc) ? _hi : _lo; (b) = (dsc) ? _lo : _hi; } while (0)

// ============================ kernel 1: GEMM pipeline ============================
__global__ void __launch_bounds__(NT1, 2)
enc_gemm(const float* __restrict__ x,  const float* __restrict__ W1,
         const float* __restrict__ b1, const float* __restrict__ W2,
         const float* __restrict__ b2, const float* __restrict__ W3,
         const float* __restrict__ b3) {
    extern __shared__ char smem[];
    float*    b1s = (float*)(smem + OFF_B1);
    float*    b2s = (float*)(smem + OFF_B2);
    float*    b3s = (float*)(smem + OFF_B3);
    __half*   W3t = (__half*)(smem + OFF_W3T);
    __half*   W2t = (__half*)(smem + OFF_W2T);
    uint32_t* zth = (uint32_t*)(smem + OFF_H1);   // overlaps h1 (dead during L3/copy)

    const int tid  = threadIdx.x;
    const int w    = tid >> 5;
    const int lane = tid & 31;
    const int g    = lane >> 2, t = lane & 3;
    const int grid = gridDim.x;

    // tiles: L1/L2 64x32; L3 32x16
    const int wm  = (w & 1) * 64, wn = (w >> 1) * 32;
    const int wm3 = (w & 3) * 32, wn3 = (w >> 2) * 16;

    const int mi   = lane >> 3;
    const int arow = (mi & 1) * 8 + (lane & 7);
    const int acol = (mi >> 1) * 8;

    const uint32_t smem_u32 = (uint32_t)__cvta_generic_to_shared(smem);
    const uint32_t aB2 = smem_u32 + OFF_H1  + ((wm  + arow) * SH + acol) * 2;  // A: h1
    const uint32_t bB2 = smem_u32 + OFF_W2T + ((wn  + arow) * SH + acol) * 2;  // B: W2t
    const uint32_t aB3 = smem_u32 + OFF_H2  + ((wm3 + arow) * SH + acol) * 2;  // A: h2
    const uint32_t sB1 = smem_u32 + OFF_H1  + ((wm  + arow) * SH + wn + acol) * 2;
    const uint32_t sB2 = smem_u32 + OFF_H2  + ((wm  + arow) * SH + wn + acol) * 2;

    // ---------------- prologue ----------------
    for (int i = tid; i < 16384; i += NT1) {   // W2t[n][k] = W2[k][n]
        int k = i >> 7, n = i & 127;
        W2t[n * SH + k] = __float2half(W2[i]);
    }
    for (int i = tid; i < 4096; i += NT1) {    // W3t[n][k] = W3[k][n]
        int k = i >> 5, n = i & 31;
        W3t[n * SH + k] = __float2half(W3[i]);
    }
    if (tid < 128) { b1s[tid] = b1[tid]; b2s[tid] = b2[tid]; }
    if (tid < 32)  b3s[tid] = b3[tid];
    __syncthreads();

    // persistent W1 fragments (4 regs)
    uint32_t bW1[4];
#pragma unroll
    for (int nt = 0; nt < 4; nt++) {
        int n = wn + 8 * nt + g;
        bW1[nt] = (t < 2) ? packh2(W1[(2 * t) * 128 + n], W1[(2 * t + 1) * 128 + n]) : 0u;
    }

    for (int b = blockIdx.x; b < NB; b += grid) {
        const float* xb = x + (size_t)b * 512;

        // ---- layer 1: h1 = relu(x @ W1 + b1); per-ms liveness ----
        {
            uint32_t a1[4][2];
#pragma unroll
            for (int ms = 0; ms < 4; ms++) {
                int row = wm + 16 * ms + g;
                if (t < 2) {
                    float2 v0 = *(const float2*)&xb[row * 4 + 2 * t];
                    float2 v1 = *(const float2*)&xb[(row + 8) * 4 + 2 * t];
                    a1[ms][0] = packh2(v0.x, v0.y);
                    a1[ms][1] = packh2(v1.x, v1.y);
                } else { a1[ms][0] = 0u; a1[ms][1] = 0u; }
            }
#pragma unroll
            for (int ms = 0; ms < 4; ms++) {
                float acc[16];
#pragma unroll
                for (int i = 0; i < 16; i++) acc[i] = 0.f;
#pragma unroll
                for (int nt = 0; nt < 4; nt++)
                    mma16808(&acc[nt * 4], a1[ms], bW1[nt]);
#pragma unroll
                for (int nh = 0; nh < 2; nh++) {
                    int c0 = wn + 16 * nh + 2 * t;
                    float bb0 = b1s[c0], bb1 = b1s[c0 + 1];
                    float bb2 = b1s[c0 + 8], bb3 = b1s[c0 + 9];
                    float* aA = &acc[(2 * nh) * 4];
                    float* aB = &acc[(2 * nh + 1) * 4];
                    uint32_t p0 = packh2(fmaxf(aA[0] + bb0, 0.f), fmaxf(aA[1] + bb1, 0.f));
                    uint32_t p1 = packh2(fmaxf(aA[2] + bb0, 0.f), fmaxf(aA[3] + bb1, 0.f));
                    uint32_t p2 = packh2(fmaxf(aB[0] + bb2, 0.f), fmaxf(aB[1] + bb3, 0.f));
                    uint32_t p3 = packh2(fmaxf(aB[2] + bb2, 0.f), fmaxf(aB[3] + bb3, 0.f));
                    STSM4(sB1 + (16 * ms * SH + 16 * nh) * 2, p0, p1, p2, p3);
                }
            }
        }
        __syncthreads();

        // ---- layer 2: h2 = relu(h1 @ W2 + b2); both operands streamed (ldmatrix) ----
        {
            float acc[64];
#pragma unroll
            for (int i = 0; i < 64; i++) acc[i] = 0.f;
#pragma unroll
            for (int ks = 0; ks < 8; ks++) {
                uint32_t af[4][4], bq[2][4];
#pragma unroll
                for (int ms = 0; ms < 4; ms++)
                    LDSM4(af[ms], aB2 + (16 * ms * SH + 16 * ks) * 2);
#pragma unroll
                for (int nb = 0; nb < 2; nb++)
                    LDSM4(bq[nb], bB2 + (16 * nb * SH + 16 * ks) * 2);
#pragma unroll
                for (int ms = 0; ms < 4; ms++)
#pragma unroll
                    for (int nt = 0; nt < 4; nt++) {
                        uint32_t bf[2] = { bq[nt >> 1][nt & 1], bq[nt >> 1][(nt & 1) + 2] };
                        mma16816(&acc[(ms * 4 + nt) * 4], af[ms], bf);
                    }
            }
#pragma unroll
            for (int ms = 0; ms < 4; ms++)
#pragma unroll
                for (int nh = 0; nh < 2; nh++) {
                    int c0 = wn + 16 * nh + 2 * t;
                    float bb0 = b2s[c0], bb1 = b2s[c0 + 1];
                    float bb2 = b2s[c0 + 8], bb3 = b2s[c0 + 9];
                    float* aA = &acc[(ms * 4 + 2 * nh) * 4];
                    float* aB = &acc[(ms * 4 + 2 * nh + 1) * 4];
                    uint32_t p0 = packh2(fmaxf(aA[0] + bb0, 0.f), fmaxf(aA[1] + bb1, 0.f));
                    uint32_t p1 = packh2(fmaxf(aA[2] + bb0, 0.f), fmaxf(aA[3] + bb1, 0.f));
                    uint32_t p2 = packh2(fmaxf(aB[0] + bb2, 0.f), fmaxf(aB[1] + bb3, 0.f));
                    uint32_t p3 = packh2(fmaxf(aB[2] + bb2, 0.f), fmaxf(aB[3] + bb3, 0.f));
                    STSM4(sB2 + (16 * ms * SH + 16 * nh) * 2, p0, p1, p2, p3);
                }
        }
        __syncthreads();

        // ---- layer 3: z^T = h2 @ W3 + b3 -> zth (h1 region, half2 channel pairs) ----
        {
            float acc3[16];
#pragma unroll
            for (int i = 0; i < 16; i++) acc3[i] = 0.f;
#pragma unroll
            for (int ks = 0; ks < 8; ks++) {
                uint32_t a3[2][4], bf[2][2];
                LDSM4(a3[0], aB3 + (16 * ks) * 2);
                LDSM4(a3[1], aB3 + (16 * SH + 16 * ks) * 2);
#pragma unroll
                for (int nt = 0; nt < 2; nt++) {
                    const __half* bp = W3t + (wn3 + 8 * nt + g) * SH + 16 * ks + 2 * t;
                    bf[nt][0] = *(const uint32_t*)(bp);
                    bf[nt][1] = *(const uint32_t*)(bp + 8);
                }
                mma16816(&acc3[0],  a3[0], bf[0]);
                mma16816(&acc3[4],  a3[0], bf[1]);
                mma16816(&acc3[8],  a3[1], bf[0]);
                mma16816(&acc3[12], a3[1], bf[1]);
            }
#pragma unroll
            for (int ms = 0; ms < 2; ms++)
#pragma unroll
                for (int nt = 0; nt < 2; nt++) {
                    int r  = wm3 + 16 * ms + g;
                    int c  = wn3 + 8 * nt + 2 * t;
                    int cp = c >> 1;
                    float* a = &acc3[(ms * 2 + nt) * 4];
                    float bb0 = b3s[c], bb1 = b3s[c + 1];
                    zth[cp * ZSTH + r]     = packh2(a[0] + bb0, a[1] + bb1);
                    zth[cp * ZSTH + r + 8] = packh2(a[2] + bb0, a[3] + bb1);
                }
        }
        __syncthreads();

        // ---- coalesced z dump: zth -> g_z[b] (2048 uint32 = 512 uint4) ----
#pragma unroll
        for (int k = 0; k < 2; k++) {
            int u = tid + k * NT1;
            int cp = u >> 5, col4 = u & 31;
            uint4 val = *(const uint4*)&zth[cp * ZSTH + col4 * 4];
            g_z[((size_t)b * 16 + cp) * 32 + col4] = val;
        }
        __syncthreads();   // zth free before next iteration's h1 writes
    }
}

// ============================ kernel 2: sort + pool + reparam ============================
__global__ void __launch_bounds__(128)
enc_sort(const float* __restrict__ pw, const float* __restrict__ eps,
         float* __restrict__ out) {
    const int b    = blockIdx.x;
    const int w    = threadIdx.x >> 5;   // 0..3
    const int lane = threadIdx.x & 31;

    // FSPool weights: stream q -> pair-row cp = 4w+q -> channels (2cp, 2cp+1)
    float wlo[4][4], whi[4][4];
#pragma unroll
    for (int q = 0; q < 4; q++) {
        int c0 = 2 * (4 * w + q);
#pragma unroll
        for (int j = 0; j < 4; j++) {
            int p = 4 * lane + j;
            float pos = (float)p * (20.0f / 127.0f);
            int idx = (int)pos; if (idx > 20) idx = 20;
            float frac = pos - (float)idx;
            int idx2 = idx + 1; if (idx2 > 20) idx2 = 20;
            wlo[q][j] = (1.0f - frac) * pw[c0 * 21 + idx]       + frac * pw[c0 * 21 + idx2];
            whi[q][j] = (1.0f - frac) * pw[(c0 + 1) * 21 + idx] + frac * pw[(c0 + 1) * 21 + idx2];
        }
    }

    float ev = 0.f;
    if (lane < 4) ev = eps[(size_t)b * 16 + 4 * w + lane];

    uint32_t v[4][4];
#pragma unroll
    for (int q = 0; q < 4; q++) {
        uint4 qd = g_z[((size_t)b * 16 + 4 * w + q) * 32 + lane];
        v[q][0] = qd.x; v[q][1] = qd.y; v[q][2] = qd.z; v[q][3] = qd.w;
    }

    // bitonic sort descending, element e = 4*lane + j, 4 half2 streams
#pragma unroll
    for (int q = 0; q < 4; q++) { CEXH(v[q][0], v[q][1], true); CEXH(v[q][2], v[q][3], false); }
    {
        const bool dsc = (lane & 1) == 0;
#pragma unroll
        for (int q = 0; q < 4; q++) { CEXH(v[q][0], v[q][2], dsc); CEXH(v[q][1], v[q][3], dsc); }
#pragma unroll
        for (int q = 0; q < 4; q++) { CEXH(v[q][0], v[q][1], dsc); CEXH(v[q][2], v[q][3], dsc); }
    }
#pragma unroll
    for (int kk = 8; kk <= 128; kk <<= 1) {
        const bool dsc = (lane & (kk >> 2)) == 0;
#pragma unroll
        for (int d = kk >> 1; d >= 4; d >>= 1) {
            const bool keep = dsc == ((lane & (d >> 2)) == 0);
#pragma unroll
            for (int q = 0; q < 4; q++)
#pragma unroll
                for (int j = 0; j < 4; j++) {
                    uint32_t pv = __shfl_xor_sync(0xffffffffu, v[q][j], d >> 2);
                    v[q][j] = keep ? h2max(v[q][j], pv) : h2min(v[q][j], pv);
                }
        }
#pragma unroll
        for (int q = 0; q < 4; q++) { CEXH(v[q][0], v[q][2], dsc); CEXH(v[q][1], v[q][3], dsc); }
#pragma unroll
        for (int q = 0; q < 4; q++) { CEXH(v[q][0], v[q][1], dsc); CEXH(v[q][2], v[q][3], dsc); }
    }

    // weighted pool; stream q = latent 4w+q (lo->mu, hi->logvar)
    float s[8];
#pragma unroll
    for (int q = 0; q < 4; q++) {
        float slo = 0.f, shi = 0.f;
#pragma unroll
        for (int j = 0; j < 4; j++) {
            float2 f = __half22float2(*(__half2*)&v[q][j]);
            slo += f.x * wlo[q][j];
            shi += f.y * whi[q][j];
        }
        s[2 * q] = slo; s[2 * q + 1] = shi;
    }
#pragma unroll
    for (int off = 16; off > 0; off >>= 1)
#pragma unroll
        for (int i = 0; i < 8; i++)
            s[i] += __shfl_xor_sync(0xffffffffu, s[i], off);

    if (lane < 4) {
        const int l = 4 * w + lane;
        float mu = s[2 * lane];
        float lv = s[2 * lane + 1];
        float sp = mu + ev * expf(0.5f * lv);
        out[(size_t)b * 16 + l]                       = mu;
        out[(size_t)NB * 16 + (size_t)b * 16 + l]     = lv;
        out[(size_t)2 * NB * 16 + (size_t)b * 16 + l] = sp;
    }
}

extern "C" void kernel_launch(void* const* d_in, const int* in_sizes, int n_in,
                              void* d_out, int out_size) {
    const float* x   = (const float*)d_in[0];
    const float* W1  = (const float*)d_in[1];
    const float* b1  = (const float*)d_in[2];
    const float* W2  = (const float*)d_in[3];
    const float* b2  = (const float*)d_in[4];
    const float* W3  = (const float*)d_in[5];
    const float* b3  = (const float*)d_in[6];
    const float* pw  = (const float*)d_in[7];
    const float* eps = (const float*)d_in[8];
    float* out = (float*)d_out;

    int dev = 0;
    cudaGetDevice(&dev);
    int nsm = 148;
    cudaDeviceGetAttribute(&nsm, cudaDevAttrMultiProcessorCount, dev);
    cudaFuncSetAttribute(enc_gemm, cudaFuncAttributeMaxDynamicSharedMemorySize, SMEM1);
    enc_gemm<<<2 * nsm, NT1, SMEM1>>>(x, W1, b1, W2, b2, W3, b3);
    enc_sort<<<NB, 128>>>(pw, eps, out);
}

// round 15
// speedup vs baseline: 1.0639x; 1.0639x over previous
#include <cuda_runtime.h>
#include <cuda_fp16.h>
#include <cstdint>

#define NB    8192
#define SH    136
#define ZSTH  136
#define NT1   256

// ---- shared memory (per CTA ~112KB -> 2 CTAs/SM) ----
#define OFF_B1   0
#define OFF_B2   512
#define OFF_B3   1024
#define OFF_W3T  1280     // 8704
#define OFF_H1   9984     // 34816 (zth overlaps this region after L2 consumes h1)
#define OFF_H2   44800    // 34816
#define OFF_W2T  79616    // 34816
#define SMEM1    114432

// precomputed FSPool weights (16 pair-rows x 128 ranks), fp32, L2-resident
__device__ float g_wl[16 * 128];
__device__ float g_wh[16 * 128];

__device__ __forceinline__ void mma16816(float* d, const uint32_t* a, const uint32_t* b) {
    asm volatile(
        "mma.sync.aligned.m16n8k16.row.col.f32.f16.f16.f32 "
        "{%0,%1,%2,%3},{%4,%5,%6,%7},{%8,%9},{%0,%1,%2,%3};\n"
        : "+f"(d[0]), "+f"(d[1]), "+f"(d[2]), "+f"(d[3])
        : "r"(a[0]), "r"(a[1]), "r"(a[2]), "r"(a[3]), "r"(b[0]), "r"(b[1]));
}

__device__ __forceinline__ void mma16808(float* d, const uint32_t* a, uint32_t b) {
    asm volatile(
        "mma.sync.aligned.m16n8k8.row.col.f32.f16.f16.f32 "
        "{%0,%1,%2,%3},{%4,%5},{%6},{%0,%1,%2,%3};\n"
        : "+f"(d[0]), "+f"(d[1]), "+f"(d[2]), "+f"(d[3])
        : "r"(a[0]), "r"(a[1]), "r"(b));
}

#define LDSM4(r, addr) \
    asm volatile("ldmatrix.sync.aligned.m8n8.x4.shared.b16 {%0,%1,%2,%3}, [%4];" \
                 : "=r"((r)[0]), "=r"((r)[1]), "=r"((r)[2]), "=r"((r)[3]) : "r"(addr))

#define STSM4(addr, r0, r1, r2, r3) \
    asm volatile("stmatrix.sync.aligned.m8n8.x4.shared.b16 [%0], {%1,%2,%3,%4};" \
                 :: "r"(addr), "r"(r0), "r"(r1), "r"(r2), "r"(r3))

__device__ __forceinline__ uint32_t packh2(float a, float b) {
    __half2 h = __floats2half2_rn(a, b);
    return *(uint32_t*)&h;
}
__device__ __forceinline__ uint32_t h2max(uint32_t a, uint32_t b) {
    __half2 r = __hmax2(*(__half2*)&a, *(__half2*)&b); return *(uint32_t*)&r;
}
__device__ __forceinline__ uint32_t h2min(uint32_t a, uint32_t b) {
    __half2 r = __hmin2(*(__half2*)&a, *(__half2*)&b); return *(uint32_t*)&r;
}
#define CEXH(a, b, dsc) do { uint32_t _hi = h2max(a, b), _lo = h2min(a, b); \
                             (a) = (dsc) ? _hi : _lo; (b) = (dsc) ? _lo : _hi; } while (0)

// ============================ kernel 0: FSPool weight precompute ============================
__global__ void enc_init(const float* __restrict__ pw) {
    int i = blockIdx.x * blockDim.x + threadIdx.x;
    if (i < 2048) {
        int cp = i >> 7, r = i & 127;
        float pos = (float)r * (20.0f / 127.0f);
        int idx = (int)pos; if (idx > 20) idx = 20;
        float frac = pos - (float)idx;
        int idx2 = idx + 1; if (idx2 > 20) idx2 = 20;
        g_wl[i] = (1.0f - frac) * pw[(2 * cp) * 21 + idx]     + frac * pw[(2 * cp) * 21 + idx2];
        g_wh[i] = (1.0f - frac) * pw[(2 * cp + 1) * 21 + idx] + frac * pw[(2 * cp + 1) * 21 + idx2];
    }
}

// ============================ kernel 1: fused pipeline ============================
__global__ void __launch_bounds__(NT1, 2)
enc_kernel(const float* __restrict__ x,  const float* __restrict__ W1,
           const float* __restrict__ b1, const float* __restrict__ W2,
           const float* __restrict__ b2, const float* __restrict__ W3,
           const float* __restrict__ b3, const float* __restrict__ eps,
           float* __restrict__ out) {
    extern __shared__ char smem[];
    float*    b1s = (float*)(smem + OFF_B1);
    float*    b2s = (float*)(smem + OFF_B2);
    float*    b3s = (float*)(smem + OFF_B3);
    __half*   W3t = (__half*)(smem + OFF_W3T);
    __half*   W2t = (__half*)(smem + OFF_W2T);
    uint32_t* zth = (uint32_t*)(smem + OFF_H1);   // overlaps h1 (dead during L3/sort)

    const int tid  = threadIdx.x;
    const int w    = tid >> 5;
    const int lane = tid & 31;
    const int g    = lane >> 2, t = lane & 3;
    const int grid = gridDim.x;

    const int wm  = (w & 1) * 64, wn = (w >> 1) * 32;   // L1/L2 tiles 64x32
    const int wm3 = (w & 3) * 32, wn3 = (w >> 2) * 16;  // L3 tiles 32x16

    const int mi   = lane >> 3;
    const int arow = (mi & 1) * 8 + (lane & 7);
    const int acol = (mi >> 1) * 8;

    const uint32_t smem_u32 = (uint32_t)__cvta_generic_to_shared(smem);
    const uint32_t aB2 = smem_u32 + OFF_H1  + ((wm  + arow) * SH + acol) * 2;
    const uint32_t bB2 = smem_u32 + OFF_W2T + ((wn  + arow) * SH + acol) * 2;
    const uint32_t aB3 = smem_u32 + OFF_H2  + ((wm3 + arow) * SH + acol) * 2;
    const uint32_t sB1 = smem_u32 + OFF_H1  + ((wm  + arow) * SH + wn + acol) * 2;
    const uint32_t sB2 = smem_u32 + OFF_H2  + ((wm  + arow) * SH + wn + acol) * 2;

    // ---------------- prologue ----------------
    for (int i = tid; i < 16384; i += NT1) {   // W2t[n][k] = W2[k][n]
        int k = i >> 7, n = i & 127;
        W2t[n * SH + k] = __float2half(W2[i]);
    }
    for (int i = tid; i < 4096; i += NT1) {    // W3t[n][k] = W3[k][n]
        int k = i >> 5, n = i & 31;
        W3t[n * SH + k] = __float2half(W3[i]);
    }
    if (tid < 128) { b1s[tid] = b1[tid]; b2s[tid] = b2[tid]; }
    if (tid < 32)  b3s[tid] = b3[tid];
    __syncthreads();

    uint32_t bW1[4];
#pragma unroll
    for (int nt = 0; nt < 4; nt++) {
        int n = wn + 8 * nt + g;
        bW1[nt] = (t < 2) ? packh2(W1[(2 * t) * 128 + n], W1[(2 * t + 1) * 128 + n]) : 0u;
    }

    for (int b = blockIdx.x; b < NB; b += grid) {
        const float* xb = x + (size_t)b * 512;

        // eps prefetch (consumed in the sort phase)
        float ev = 0.f;
        if (lane < 2) ev = eps[(size_t)b * 16 + 2 * w + lane];

        // ---- layer 1: h1 = relu(x @ W1 + b1); per-ms liveness ----
        {
            uint32_t a1[4][2];
#pragma unroll
            for (int ms = 0; ms < 4; ms++) {
                int row = wm + 16 * ms + g;
                if (t < 2) {
                    float2 v0 = *(const float2*)&xb[row * 4 + 2 * t];
                    float2 v1 = *(const float2*)&xb[(row + 8) * 4 + 2 * t];
                    a1[ms][0] = packh2(v0.x, v0.y);
                    a1[ms][1] = packh2(v1.x, v1.y);
                } else { a1[ms][0] = 0u; a1[ms][1] = 0u; }
            }
#pragma unroll
            for (int ms = 0; ms < 4; ms++) {
                float acc[16];
#pragma unroll
                for (int i = 0; i < 16; i++) acc[i] = 0.f;
#pragma unroll
                for (int nt = 0; nt < 4; nt++)
                    mma16808(&acc[nt * 4], a1[ms], bW1[nt]);
#pragma unroll
                for (int nh = 0; nh < 2; nh++) {
                    int c0 = wn + 16 * nh + 2 * t;
                    float bb0 = b1s[c0], bb1 = b1s[c0 + 1];
                    float bb2 = b1s[c0 + 8], bb3 = b1s[c0 + 9];
                    float* aA = &acc[(2 * nh) * 4];
                    float* aB = &acc[(2 * nh + 1) * 4];
                    uint32_t p0 = packh2(fmaxf(aA[0] + bb0, 0.f), fmaxf(aA[1] + bb1, 0.f));
                    uint32_t p1 = packh2(fmaxf(aA[2] + bb0, 0.f), fmaxf(aA[3] + bb1, 0.f));
                    uint32_t p2 = packh2(fmaxf(aB[0] + bb2, 0.f), fmaxf(aB[1] + bb3, 0.f));
                    uint32_t p3 = packh2(fmaxf(aB[2] + bb2, 0.f), fmaxf(aB[3] + bb3, 0.f));
                    STSM4(sB1 + (16 * ms * SH + 16 * nh) * 2, p0, p1, p2, p3);
                }
            }
        }
        __syncthreads();

        // ---- layer 2: h2 = relu(h1 @ W2 + b2); both operands streamed via ldmatrix ----
        {
            float acc[64];
#pragma unroll
            for (int i = 0; i < 64; i++) acc[i] = 0.f;
#pragma unroll
            for (int ks = 0; ks < 8; ks++) {
                uint32_t af[4][4], bq[2][4];
#pragma unroll
                for (int ms = 0; ms < 4; ms++)
                    LDSM4(af[ms], aB2 + (16 * ms * SH + 16 * ks) * 2);
#pragma unroll
                for (int nb = 0; nb < 2; nb++)
                    LDSM4(bq[nb], bB2 + (16 * nb * SH + 16 * ks) * 2);
#pragma unroll
                for (int ms = 0; ms < 4; ms++)
#pragma unroll
                    for (int nt = 0; nt < 4; nt++) {
                        uint32_t bf[2] = { bq[nt >> 1][nt & 1], bq[nt >> 1][(nt & 1) + 2] };
                        mma16816(&acc[(ms * 4 + nt) * 4], af[ms], bf);
                    }
            }
#pragma unroll
            for (int ms = 0; ms < 4; ms++)
#pragma unroll
                for (int nh = 0; nh < 2; nh++) {
                    int c0 = wn + 16 * nh + 2 * t;
                    float bb0 = b2s[c0], bb1 = b2s[c0 + 1];
                    float bb2 = b2s[c0 + 8], bb3 = b2s[c0 + 9];
                    float* aA = &acc[(ms * 4 + 2 * nh) * 4];
                    float* aB = &acc[(ms * 4 + 2 * nh + 1) * 4];
                    uint32_t p0 = packh2(fmaxf(aA[0] + bb0, 0.f), fmaxf(aA[1] + bb1, 0.f));
                    uint32_t p1 = packh2(fmaxf(aA[2] + bb0, 0.f), fmaxf(aA[3] + bb1, 0.f));
                    uint32_t p2 = packh2(fmaxf(aB[0] + bb2, 0.f), fmaxf(aB[1] + bb3, 0.f));
                    uint32_t p3 = packh2(fmaxf(aB[2] + bb2, 0.f), fmaxf(aB[3] + bb3, 0.f));
                    STSM4(sB2 + (16 * ms * SH + 16 * nh) * 2, p0, p1, p2, p3);
                }
        }
        __syncthreads();

        // ---- layer 3: z^T = h2 @ W3 + b3 -> zth (h1 region, half2 channel pairs) ----
        {
            float acc3[16];
#pragma unroll
            for (int i = 0; i < 16; i++) acc3[i] = 0.f;
#pragma unroll
            for (int ks = 0; ks < 8; ks++) {
                uint32_t a3[2][4], bf[2][2];
                LDSM4(a3[0], aB3 + (16 * ks) * 2);
                LDSM4(a3[1], aB3 + (16 * SH + 16 * ks) * 2);
#pragma unroll
                for (int nt = 0; nt < 2; nt++) {
                    const __half* bp = W3t + (wn3 + 8 * nt + g) * SH + 16 * ks + 2 * t;
                    bf[nt][0] = *(const uint32_t*)(bp);
                    bf[nt][1] = *(const uint32_t*)(bp + 8);
                }
                mma16816(&acc3[0],  a3[0], bf[0]);
                mma16816(&acc3[4],  a3[0], bf[1]);
                mma16816(&acc3[8],  a3[1], bf[0]);
                mma16816(&acc3[12], a3[1], bf[1]);
            }
#pragma unroll
            for (int ms = 0; ms < 2; ms++)
#pragma unroll
                for (int nt = 0; nt < 2; nt++) {
                    int r  = wm3 + 16 * ms + g;
                    int c  = wn3 + 8 * nt + 2 * t;
                    int cp = c >> 1;
                    float* a = &acc3[(ms * 2 + nt) * 4];
                    float bb0 = b3s[c], bb1 = b3s[c + 1];
                    zth[cp * ZSTH + r]     = packh2(a[0] + bb0, a[1] + bb1);
                    zth[cp * ZSTH + r + 8] = packh2(a[2] + bb0, a[3] + bb1);
                }
        }
        __syncthreads();

        // ---- sort + pool + output: 2 half2 streams/warp (pair-rows 2w, 2w+1) ----
        {
            uint32_t v[2][4];
#pragma unroll
            for (int q = 0; q < 2; q++) {
                uint4 qd = *(const uint4*)&zth[(2 * w + q) * ZSTH + 4 * lane];
                v[q][0] = qd.x; v[q][1] = qd.y; v[q][2] = qd.z; v[q][3] = qd.w;
            }
            // k=2
#pragma unroll
            for (int q = 0; q < 2; q++) { CEXH(v[q][0], v[q][1], true); CEXH(v[q][2], v[q][3], false); }
            // k=4
            {
                const bool dsc = (lane & 1) == 0;
#pragma unroll
                for (int q = 0; q < 2; q++) { CEXH(v[q][0], v[q][2], dsc); CEXH(v[q][1], v[q][3], dsc); }
#pragma unroll
                for (int q = 0; q < 2; q++) { CEXH(v[q][0], v[q][1], dsc); CEXH(v[q][2], v[q][3], dsc); }
            }
            // k = 8..128
#pragma unroll
            for (int kk = 8; kk <= 128; kk <<= 1) {
                const bool dsc = (lane & (kk >> 2)) == 0;
#pragma unroll
                for (int d = kk >> 1; d >= 4; d >>= 1) {
                    const bool keep = dsc == ((lane & (d >> 2)) == 0);
#pragma unroll
                    for (int q = 0; q < 2; q++)
#pragma unroll
                        for (int j = 0; j < 4; j++) {
                            uint32_t pv = __shfl_xor_sync(0xffffffffu, v[q][j], d >> 2);
                            v[q][j] = keep ? h2max(v[q][j], pv) : h2min(v[q][j], pv);
                        }
                }
#pragma unroll
                for (int q = 0; q < 2; q++) { CEXH(v[q][0], v[q][2], dsc); CEXH(v[q][1], v[q][3], dsc); }
#pragma unroll
                for (int q = 0; q < 2; q++) { CEXH(v[q][0], v[q][1], dsc); CEXH(v[q][2], v[q][3], dsc); }
            }
            // weighted pool: rank r = 4*lane+j, weights from L2-resident globals
            float s[4];
#pragma unroll
            for (int q = 0; q < 2; q++) {
                float4 wlv = *(const float4*)&g_wl[(2 * w + q) * 128 + 4 * lane];
                float4 whv = *(const float4*)&g_wh[(2 * w + q) * 128 + 4 * lane];
                float2 f0 = __half22float2(*(__half2*)&v[q][0]);
                float2 f1 = __half22float2(*(__half2*)&v[q][1]);
                float2 f2 = __half22float2(*(__half2*)&v[q][2]);
                float2 f3 = __half22float2(*(__half2*)&v[q][3]);
                s[2 * q]     = f0.x * wlv.x + f1.x * wlv.y + f2.x * wlv.z + f3.x * wlv.w;
                s[2 * q + 1] = f0.y * whv.x + f1.y * whv.y + f2.y * whv.z + f3.y * whv.w;
            }
#pragma unroll
            for (int off = 16; off > 0; off >>= 1)
#pragma unroll
                for (int i = 0; i < 4; i++)
                    s[i] += __shfl_xor_sync(0xffffffffu, s[i], off);

            if (lane < 2) {
                const int l = 2 * w + lane;
                float mu = s[2 * lane];
                float lv = s[2 * lane + 1];
                float sp = mu + ev * expf(0.5f * lv);
                out[(size_t)b * 16 + l]                       = mu;
                out[(size_t)NB * 16 + (size_t)b * 16 + l]     = lv;
                out[(size_t)2 * NB * 16 + (size_t)b * 16 + l] = sp;
            }
        }
        __syncthreads();   // zth (= h1 region) must be free before next L1 writes
    }
}

extern "C" void kernel_launch(void* const* d_in, const int* in_sizes, int n_in,
                              void* d_out, int out_size) {
    const float* x   = (const float*)d_in[0];
    const float* W1  = (const float*)d_in[1];
    const float* b1  = (const float*)d_in[2];
    const float* W2  = (const float*)d_in[3];
    const float* b2  = (const float*)d_in[4];
    const float* W3  = (const float*)d_in[5];
    const float* b3  = (const float*)d_in[6];
    const float* pw  = (const float*)d_in[7];
    const float* eps = (const float*)d_in[8];
    float* out = (float*)d_out;

    int dev = 0;
    cudaGetDevice(&dev);
    int nsm = 148;
    cudaDeviceGetAttribute(&nsm, cudaDevAttrMultiProcessorCount, dev);
    cudaFuncSetAttribute(enc_kernel, cudaFuncAttributeMaxDynamicSharedMemorySize, SMEM1);

    enc_init<<<8, 256>>>(pw);
    enc_kernel<<<2 * nsm, NT1, SMEM1>>>(x, W1, b1, W2, b2, W3, b3, eps, out);
}